// round 8
// baseline (speedup 1.0000x reference)
#include <cuda_runtime.h>
#include <cuda_fp16.h>
#include <cstdint>

#define NB 4
#define NN 10000
#define NE 160000
#define NQ 256
#define ND 128
#define NM 64
#define NU 126
#define NH 128
#define NP 7
#define OUTC (NP + ND)   // 135

#define TEE 128                    // edges per edge-tile
#define NTE_B (NE / TEE)           // 1250
#define NTE_TOT (NTE_B * NB)       // 5000

#define NT_NODE_B 157              // ceil(10000/64)
#define NT_NODE_TOT (NT_NODE_B * NB)

#define NPT_B 79                   // ceil(10000/128) proj tiles per batch
#define NPT_TOT (NPT_B * NB)       // 316

// -------- scratch (static device globals: allocation-free) --------
__device__ float g_states[NB * NN * ND];                  // 20.5 MB
__device__ __align__(16) __half g_statesH[NB * NN * ND];  // 10.2 MB fp16 mirror
__device__ float g_incoming[NB * NN * NM];                // 10.2 MB
__device__ __align__(16) __half g_P1[NB * NN * NH];       // 10.2 MB src projections
__device__ __align__(16) __half g_P2[NB * NN * NH];       // 10.2 MB snk projections
// CSR scratch
__device__ int g_count[NN];
__device__ int g_cur[NN];
__device__ int g_sortedSrc[NE];
__device__ int g_sortedSnk[NE];

// ============================ helpers ============================
__device__ __forceinline__ uint32_t smem_u32(const void* p) {
    uint32_t a;
    asm("{ .reg .u64 t; cvta.to.shared.u64 t, %1; cvt.u32.u64 %0, t; }"
        : "=r"(a) : "l"(p));
    return a;
}
__device__ __forceinline__ uint32_t pack_h2(float a, float b) {
    __half2 h = __floats2half2_rn(a, b);
    return *reinterpret_cast<uint32_t*>(&h);
}
__device__ __forceinline__ void mma_f16(float* c, uint32_t a0, uint32_t a1,
                                        uint32_t a2, uint32_t a3,
                                        uint32_t b0, uint32_t b1) {
    asm volatile(
        "mma.sync.aligned.m16n8k16.row.col.f32.f16.f16.f32 "
        "{%0,%1,%2,%3}, {%4,%5,%6,%7}, {%8,%9}, {%0,%1,%2,%3};"
        : "+f"(c[0]), "+f"(c[1]), "+f"(c[2]), "+f"(c[3])
        : "r"(a0), "r"(a1), "r"(a2), "r"(a3), "r"(b0), "r"(b1));
}
#define CP_ASYNC16(dst, src) \
    asm volatile("cp.async.cg.shared.global [%0], [%1], 16;" \
                 :: "r"(dst), "l"(src) : "memory")
#define CP_COMMIT() asm volatile("cp.async.commit_group;" ::: "memory")
#define CP_WAIT0()  asm volatile("cp.async.wait_group 0;" ::: "memory")

// -------- utility kernels --------
__global__ void copy_states_kernel(const float* __restrict__ src) {
    int i = blockIdx.x * blockDim.x + threadIdx.x;
    const int n = NB * NN * ND / 4;
    if (i < n) {
        float4 v = reinterpret_cast<const float4*>(src)[i];
        reinterpret_cast<float4*>(g_states)[i] = v;
        __half2* mh = reinterpret_cast<__half2*>(g_statesH);
        mh[2 * i]     = __floats2half2_rn(v.x, v.y);
        mh[2 * i + 1] = __floats2half2_rn(v.z, v.w);
    }
}

__global__ void zero_incoming_kernel() {
    int i = blockIdx.x * blockDim.x + threadIdx.x;
    const int n = NB * NN * NM / 4;
    if (i < n) reinterpret_cast<float4*>(g_incoming)[i] = make_float4(0.f, 0.f, 0.f, 0.f);
}

__global__ void init_out_kernel(const float* __restrict__ poses, float* __restrict__ out) {
    int i = blockIdx.x * blockDim.x + threadIdx.x;
    const int n = NB * NQ * OUTC;
    if (i < n) {
        int r = i / OUTC, c = i - r * OUTC;
        out[i] = (c < NP) ? poses[r * NP + c] : 0.f;
    }
}

// -------- CSR build (once per launch) --------
__global__ void csr_zero_kernel() {
    int i = blockIdx.x * blockDim.x + threadIdx.x;
    if (i < NN) g_count[i] = 0;
}
__global__ void csr_hist_kernel(const int* __restrict__ esnk) {
    int i = blockIdx.x * blockDim.x + threadIdx.x;
    if (i < NE) atomicAdd(&g_count[esnk[i]], 1);
}
__global__ void csr_scan_kernel() {
    __shared__ int part[1024];
    int t = threadIdx.x;
    int beg = t * 10;
    int end = beg + 10 < NN ? beg + 10 : NN;
    int s = 0;
    for (int i = beg; i < end; i++) s += g_count[i];
    part[t] = s;
    __syncthreads();
    for (int d = 1; d < 1024; d <<= 1) {
        int v = (t >= d) ? part[t - d] : 0;
        __syncthreads();
        part[t] += v;
        __syncthreads();
    }
    int base = (t > 0) ? part[t - 1] : 0;
    for (int i = beg; i < end; i++) {
        g_cur[i] = base;
        base += g_count[i];
    }
}
__global__ void csr_scatter_kernel(const int* __restrict__ esrc,
                                   const int* __restrict__ esnk) {
    int i = blockIdx.x * blockDim.x + threadIdx.x;
    if (i < NE) {
        int s = esnk[i];
        int p = atomicAdd(&g_cur[s], 1);
        g_sortedSrc[p] = esrc[i];
        g_sortedSnk[p] = s;
    }
}

// =====================================================================
// Projection kernel: P1 = statesH @ W1top, P2 = statesH @ W1bot (fp16 out)
// One fused GEMM [128n x 128k] @ [128k x 256h'].
// smem (u32): PW [0,16384) frags [8 sg][32 nf][32][2];
//             PA [16384, +2*8704) A bufs [128 n][68] (128 f16 + pad)
// =====================================================================
#define PW 0
#define PA 16384
#define PROJ_SMEM_BYTES ((16384 + 2 * 8704) * 4)   // 135168

__device__ __forceinline__ void proj_issue(uint32_t aBase, int b, int n0, int tid) {
    const __half* stH = g_statesH + (size_t)b * NN * ND;
    #pragma unroll
    for (int t = 0; t < 8; t++) {
        int idx = tid + t * 256;       // 0..2047
        int row = idx >> 4, ch = idx & 15;
        int node = n0 + row;
        if (node >= NN) node = NN - 1;   // clamp; stores are guarded
        uint32_t dst = aBase + row * 272 + ch * 16;
        CP_ASYNC16(dst, stH + (size_t)node * ND + ch * 8);
    }
}

__global__ __launch_bounds__(256, 1) void proj_kernel(
    const float* __restrict__ w1)
{
    extern __shared__ uint32_t su[];
    const int tid = threadIdx.x;
    const int lid = tid & 31;
    const int wid = tid >> 5;
    const int wm = wid >> 1;     // 4 row groups of 32 nodes
    const int wn = wid & 1;      // 2 col halves of 128 h'
    const uint32_t aBase0 = smem_u32(su + PA);

    // prologue: issue tile-0 A load
    {
        int T0 = blockIdx.x;
        if (T0 < NPT_TOT) {
            int b0 = T0 / NPT_B;
            proj_issue(aBase0, b0, (T0 - b0 * NPT_B) * 128, tid);
        }
    }
    CP_COMMIT();

    // stage W1' = [W1top | W1bot] fragments
    for (int i = tid; i < 8 * 32 * 32; i += 256) {
        int s = i >> 10;            // sg
        int f = (i >> 5) & 31;      // nf (global, 0..31)
        int l = i & 31;
        int colg = f * 8 + (l >> 2);            // 0..255
        int krow = s * 16 + (l & 3) * 2;
        int koff = (colg >= 128) ? 128 : 0;
        int col = colg & 127;
        uint2 v;
        v.x = pack_h2(w1[(koff + krow) * NH + col],     w1[(koff + krow + 1) * NH + col]);
        v.y = pack_h2(w1[(koff + krow + 8) * NH + col], w1[(koff + krow + 9) * NH + col]);
        *(uint2*)(su + PW + 2 * i) = v;
    }

    int it = 0;
    for (int T = blockIdx.x; T < NPT_TOT; T += gridDim.x, it++) {
        const int b = T / NPT_B;
        const int n0 = (T - b * NPT_B) * 128;

        CP_WAIT0();
        __syncthreads();

        // issue next tile into other buffer
        {
            int Tn = T + gridDim.x;
            if (Tn < NPT_TOT) {
                int bn = Tn / NPT_B;
                proj_issue(aBase0 + ((it + 1) & 1) * 8704 * 4,
                           bn, (Tn - bn * NPT_B) * 128, tid);
            }
        }
        CP_COMMIT();

        const uint32_t* A = su + PA + (it & 1) * 8704;
        float acc[32][4];
        #pragma unroll
        for (int f = 0; f < 32; f++)
            #pragma unroll
            for (int j = 0; j < 4; j++) acc[f][j] = 0.f;

        const int r0 = wm * 32 + (lid >> 2);
        #pragma unroll
        for (int sg = 0; sg < 8; sg++) {
            const int kw = sg * 8 + (lid & 3);
            uint32_t a00 = A[r0 * 68 + kw];
            uint32_t a01 = A[(r0 + 8) * 68 + kw];
            uint32_t a02 = A[r0 * 68 + kw + 4];
            uint32_t a03 = A[(r0 + 8) * 68 + kw + 4];
            uint32_t a10 = A[(r0 + 16) * 68 + kw];
            uint32_t a11 = A[(r0 + 24) * 68 + kw];
            uint32_t a12 = A[(r0 + 16) * 68 + kw + 4];
            uint32_t a13 = A[(r0 + 24) * 68 + kw + 4];
            #pragma unroll
            for (int f = 0; f < 16; f++) {
                uint2 bp = *(const uint2*)(su + PW +
                    ((sg * 32 + wn * 16 + f) * 32 + lid) * 2);
                mma_f16(acc[f],      a00, a01, a02, a03, bp.x, bp.y);
                mma_f16(acc[16 + f], a10, a11, a12, a13, bp.x, bp.y);
            }
        }

        // store P1/P2 (fp16)
        #pragma unroll
        for (int mf = 0; mf < 2; mf++) {
            #pragma unroll
            for (int f = 0; f < 16; f++) {
                const float* c = acc[mf * 16 + f];
                int colg = wn * 128 + f * 8 + (lid & 3) * 2;
                __half* P = (colg < 128) ? g_P1 : g_P2;
                int col = colg & 127;
                int r = wm * 32 + mf * 16 + (lid >> 2);
                int node0 = n0 + r, node1 = n0 + r + 8;
                if (node0 < NN)
                    *(uint32_t*)(P + ((size_t)b * NN + node0) * NH + col) =
                        pack_h2(c[0], c[1]);
                if (node1 < NN)
                    *(uint32_t*)(P + ((size_t)b * NN + node1) * NH + col) =
                        pack_h2(c[2], c[3]);
            }
        }
        __syncthreads();
    }
}

// =====================================================================
// Edge kernel: gather P1[src], P2[snk]; h = relu(P1+P2+b1); GEMM2;
// segmented scatter. Persistent, 512 thr, 1 CTA/SM.
// smem (u32):
//   EW2   [0,4096)        W2 frags [8 sg][8 nf][32][2]    16 KB
//   EB1H  [4096,4160)     b1 as 64 half2
//   EB2   [4160,4224)     b2 fp32
//   ESNKB [4224,4480)     2 x 128 int
//   EH    [4480,13184)    H [128 e][68]  (128 f16 + pad)  34 KB
//   EMS   [13184,21888)   MSG fp32 [128 e][68]            34 KB
//   EG    [21888,55680)   gather bufs 2 x [128 e][132]    132 KB
// =====================================================================
#define EW2   0
#define EB1H  4096
#define EB2   4160
#define ESNKB 4224
#define EH    4480
#define EMS   13184
#define EG    21888
#define EDGE_SMEM_BYTES (55680 * 4)   // 222720

__device__ __forceinline__ void edge_issue(uint32_t gBase, int b, int eb, int tid) {
    const __half* P1 = g_P1 + (size_t)b * NN * NH;
    const __half* P2 = g_P2 + (size_t)b * NN * NH;
    #pragma unroll
    for (int t = 0; t < 8; t++) {
        int idx = tid + t * 512;        // 0..4095
        int row = idx >> 4;             // 0..255
        int ch  = idx & 15;
        int e   = row & 127;
        bool snk = row >= 128;
        int node = snk ? g_sortedSnk[eb + e] : g_sortedSrc[eb + e];
        const __half* P = snk ? P2 : P1;
        uint32_t dst = gBase + (uint32_t)(e * 528 + (snk ? 256 : 0) + ch * 16);
        CP_ASYNC16(dst, P + (size_t)node * NH + ch * 8);
    }
}

__global__ __launch_bounds__(512, 1) void edge_kernel(
    const float* __restrict__ b1,
    const float* __restrict__ w2, const float* __restrict__ b2)
{
    extern __shared__ uint32_t su[];
    float* sfB2 = (float*)(su + EB2);
    int* sSnkB = (int*)(su + ESNKB);

    const int tid = threadIdx.x;
    const int lid = tid & 31;
    const int wid = tid >> 5;          // 0..15
    const int wg  = wid >> 1;          // 8 groups of 16 edges
    const int wc  = wid & 1;           // column half of NM
    const uint32_t gBase0 = smem_u32(su + EG);

    // prologue: issue tile-0 gather
    {
        int T0 = blockIdx.x;
        int b0 = T0 / NTE_B;
        int eb0 = (T0 - b0 * NTE_B) * TEE;
        edge_issue(gBase0, b0, eb0, tid);
        if (tid < TEE) sSnkB[tid] = g_sortedSnk[eb0 + tid];
    }
    CP_COMMIT();

    // stage W2 frags + biases
    for (int i = tid; i < 8 * 8 * 32; i += 512) {
        int s = i >> 8, f = (i >> 5) & 7, l = i & 31;
        int k = s * 16 + (l & 3) * 2, n = f * 8 + (l >> 2);
        uint2 v;
        v.x = pack_h2(w2[k * NM + n],       w2[(k + 1) * NM + n]);
        v.y = pack_h2(w2[(k + 8) * NM + n], w2[(k + 9) * NM + n]);
        *(uint2*)(su + EW2 + 2 * i) = v;
    }
    if (tid < 64) su[EB1H + tid] = pack_h2(b1[2 * tid], b1[2 * tid + 1]);
    else if (tid < 128) sfB2[tid - 64] = b2[tid - 64];

    const int arq = wg * 16 + (lid >> 2);
    const __half2 hz = __float2half2_rn(0.f);

    int it = 0;
    for (int T = blockIdx.x; T < NTE_TOT; T += gridDim.x, it++) {
        const int b = T / NTE_B;
        float* inc = g_incoming + (size_t)b * NN * NM;

        CP_WAIT0();
        __syncthreads();   // gather buf (it&1) + sSnk + weights ready

        // ---- H = relu(P1 + P2 + b1), fp16 ----
        {
            const uint32_t* G = su + EG + (it & 1) * 16896;
            #pragma unroll
            for (int t = 0; t < 16; t++) {
                int idx = tid + t * 512;
                int e = idx >> 6, cu = idx & 63;
                __half2 p1 = *(const __half2*)(G + e * 132 + cu);
                __half2 p2 = *(const __half2*)(G + e * 132 + 64 + cu);
                __half2 bb = *(const __half2*)(su + EB1H + cu);
                __half2 h = __hmax2(__hadd2(__hadd2(p1, p2), bb), hz);
                su[EH + e * 68 + cu] = *(uint32_t*)&h;
            }
        }
        __syncthreads();   // H ready; gather buf consumed

        // ---- issue next tile's gather ----
        {
            int Tn = T + gridDim.x;
            if (Tn < NTE_TOT) {
                int bn = Tn / NTE_B;
                int ebn = (Tn - bn * NTE_B) * TEE;
                edge_issue(gBase0 + ((it + 1) & 1) * 16896 * 4, bn, ebn, tid);
                if (tid < TEE)
                    sSnkB[((it + 1) & 1) * TEE + tid] = g_sortedSnk[ebn + tid];
            }
        }
        CP_COMMIT();

        // ---- GEMM2: [128e x 128h] @ [128h x 64m] ----
        float acc2[4][4];
        #pragma unroll
        for (int f = 0; f < 4; f++)
            #pragma unroll
            for (int j = 0; j < 4; j++) acc2[f][j] = 0.f;

        #pragma unroll 4
        for (int sg = 0; sg < 8; sg++) {
            const int kw = sg * 8 + (lid & 3);
            uint32_t a0 = su[EH + arq * 68 + kw];
            uint32_t a1 = su[EH + (arq + 8) * 68 + kw];
            uint32_t a2 = su[EH + arq * 68 + kw + 4];
            uint32_t a3 = su[EH + (arq + 8) * 68 + kw + 4];
            #pragma unroll
            for (int f = 0; f < 4; f++) {
                uint2 bp = *(const uint2*)(su + EW2 +
                    ((sg * 8 + wc * 4 + f) * 32 + lid) * 2);
                mma_f16(acc2[f], a0, a1, a2, a3, bp.x, bp.y);
            }
        }

        // ---- bias -> MSG (fp32) ----
        float* sfMSG = (float*)(su + EMS);
        #pragma unroll
        for (int f = 0; f < 4; f++) {
            int m = wc * 32 + f * 8 + 2 * (lid & 3);
            float bb0 = sfB2[m], bb1 = sfB2[m + 1];
            sfMSG[arq * 68 + m]           = acc2[f][0] + bb0;
            sfMSG[arq * 68 + m + 1]       = acc2[f][1] + bb1;
            sfMSG[(arq + 8) * 68 + m]     = acc2[f][2] + bb0;
            sfMSG[(arq + 8) * 68 + m + 1] = acc2[f][3] + bb1;
        }
        __syncthreads();

        // ---- segmented reduction over sorted sinks ----
        {
            const int* sSnk = sSnkB + (it & 1) * TEE;
            const int c = tid & 63;
            const int e0s = (tid >> 6) * 16;
            float part = 0.f;
            int cur = sSnk[e0s];
            #pragma unroll
            for (int j = 0; j < 16; j++) {
                part += sfMSG[(e0s + j) * 68 + c];
                int nxt = (j < 15) ? sSnk[e0s + j + 1] : -1;
                if (nxt != cur) {
                    atomicAdd(inc + (size_t)cur * NM + c, part);
                    part = 0.f;
                    cur = nxt;
                }
            }
        }
        // next iteration's top barrier orders MSG/H reuse
    }
}

// =====================================================================
// Node kernel (persistent, fp16 mma, 2 CTAs/SM) + fp16 mirror upkeep
// =====================================================================
#define NW1 0
#define NW2 12288
#define NA  20480
#define NHS 23040
#define NB1 27392
#define NB2 27520
#define NODE_SMEM_BYTES (27648 * 4)   // 110592

__global__ __launch_bounds__(256, 2) void node_kernel(
    const float* __restrict__ w1, const float* __restrict__ b1,
    const float* __restrict__ w2, const float* __restrict__ b2)
{
    extern __shared__ uint32_t su[];
    float* sfB1 = (float*)(su + NB1);
    float* sfB2 = (float*)(su + NB2);

    const int tid = threadIdx.x;
    const int lid = tid & 31;
    const int wid = tid >> 5;
    const int wr = wid & 3;
    const int wc = wid >> 2;

    for (int i = tid; i < 12 * 16 * 32; i += 256) {
        int s = i >> 9, f = (i >> 5) & 15, l = i & 31;
        int k = s * 16 + (l & 3) * 2, n = f * 8 + (l >> 2);
        uint2 v;
        v.x = pack_h2(w1[k * NH + n],       w1[(k + 1) * NH + n]);
        v.y = pack_h2(w1[(k + 8) * NH + n], w1[(k + 9) * NH + n]);
        *(uint2*)(su + NW1 + 2 * i) = v;
    }
    for (int i = tid; i < 8 * 16 * 32; i += 256) {
        int s = i >> 9, f = (i >> 5) & 15, l = i & 31;
        int k = s * 16 + (l & 3) * 2, n = f * 8 + (l >> 2);
        uint2 v;
        if (n < NU) {
            v.x = pack_h2(w2[k * NU + n],       w2[(k + 1) * NU + n]);
            v.y = pack_h2(w2[(k + 8) * NU + n], w2[(k + 9) * NU + n]);
        } else v.x = v.y = 0u;
        *(uint2*)(su + NW2 + 2 * i) = v;
    }
    if (tid < NH) sfB1[tid] = b1[tid];
    if (tid < 128) sfB2[tid] = (tid < NU) ? b2[tid] : 0.f;
    __syncthreads();

    const int l16 = lid & 15;
    const int rhalf = lid >> 4;

    for (int T = blockIdx.x; T < NT_NODE_TOT; T += gridDim.x) {
        const int b = T / NT_NODE_B;
        const int n0 = (T - b * NT_NODE_B) * 64;
        float* st = g_states + (size_t)b * NN * ND;
        __half* stH = g_statesH + (size_t)b * NN * ND;
        const float* inc = g_incoming + (size_t)b * NN * NM;

        float acc[8][4];
        #pragma unroll
        for (int f = 0; f < 8; f++)
            #pragma unroll
            for (int j = 0; j < 4; j++) acc[f][j] = 0.f;

        float2 r[4];
        {
            #pragma unroll
            for (int i = 0; i < 4; i++) {
                int row = wid * 8 + 2 * i + rhalf;
                int node = n0 + row;
                r[i] = (node < NN) ? *(const float2*)&inc[(size_t)node * NM + l16 * 2]
                                   : make_float2(0.f, 0.f);
            }
            #pragma unroll
            for (int i = 0; i < 4; i++) {
                int row = wid * 8 + 2 * i + rhalf;
                su[NA + row * 20 + l16] = pack_h2(r[i].x, r[i].y);
            }
        }
        __syncthreads();

        const int ar = wr * 16 + (lid >> 2);
        #pragma unroll 1
        for (int c = 0; c < 6; c++) {
            if (c < 5) {
                const int cc = c + 1;
                const int g = cc * 32 + l16 * 2;
                #pragma unroll
                for (int i = 0; i < 4; i++) {
                    int row = wid * 8 + 2 * i + rhalf;
                    int node = n0 + row;
                    if (node < NN)
                        r[i] = (g < NM) ? *(const float2*)&inc[(size_t)node * NM + g]
                                        : *(const float2*)&st[(size_t)node * ND + g - NM];
                    else r[i] = make_float2(0.f, 0.f);
                }
            }
            const uint32_t* A = su + NA + (c & 1) * 1280;
            #pragma unroll
            for (int ks = 0; ks < 2; ks++) {
                const int kw = ks * 8 + (lid & 3);
                uint32_t a0 = A[ar * 20 + kw];
                uint32_t a1 = A[(ar + 8) * 20 + kw];
                uint32_t a2 = A[ar * 20 + kw + 4];
                uint32_t a3 = A[(ar + 8) * 20 + kw + 4];
                const int sg = c * 2 + ks;
                #pragma unroll
                for (int f = 0; f < 8; f++) {
                    uint2 bp = *(const uint2*)(su + NW1 +
                        ((sg * 16 + wc * 8 + f) * 32 + lid) * 2);
                    mma_f16(acc[f], a0, a1, a2, a3, bp.x, bp.y);
                }
            }
            if (c < 5) {
                uint32_t* dst = su + NA + ((c + 1) & 1) * 1280;
                #pragma unroll
                for (int i = 0; i < 4; i++) {
                    int row = wid * 8 + 2 * i + rhalf;
                    dst[row * 20 + l16] = pack_h2(r[i].x, r[i].y);
                }
            }
            __syncthreads();
        }

        {
            #pragma unroll
            for (int f = 0; f < 8; f++) {
                int nn0 = wc * 64 + f * 8 + 2 * (lid & 3);
                float bb0 = sfB1[nn0], bb1 = sfB1[nn0 + 1];
                int wcol = wc * 32 + f * 4 + (lid & 3);
                su[NHS + ar * 68 + wcol] =
                    pack_h2(fmaxf(acc[f][0] + bb0, 0.f), fmaxf(acc[f][1] + bb1, 0.f));
                su[NHS + (ar + 8) * 68 + wcol] =
                    pack_h2(fmaxf(acc[f][2] + bb0, 0.f), fmaxf(acc[f][3] + bb1, 0.f));
            }
        }
        __syncthreads();

        float acc2[8][4];
        #pragma unroll
        for (int f = 0; f < 8; f++)
            #pragma unroll
            for (int j = 0; j < 4; j++) acc2[f][j] = 0.f;

        #pragma unroll 2
        for (int ks = 0; ks < 8; ks++) {
            const int kw = ks * 8 + (lid & 3);
            uint32_t a0 = su[NHS + ar * 68 + kw];
            uint32_t a1 = su[NHS + (ar + 8) * 68 + kw];
            uint32_t a2 = su[NHS + ar * 68 + kw + 4];
            uint32_t a3 = su[NHS + (ar + 8) * 68 + kw + 4];
            #pragma unroll
            for (int f = 0; f < 8; f++) {
                uint2 bp = *(const uint2*)(su + NW2 +
                    ((ks * 16 + wc * 8 + f) * 32 + lid) * 2);
                mma_f16(acc2[f], a0, a1, a2, a3, bp.x, bp.y);
            }
        }

        {
            const int node0 = n0 + ar, node1 = n0 + ar + 8;
            #pragma unroll
            for (int f = 0; f < 8; f++) {
                int cc = wc * 64 + f * 8 + 2 * (lid & 3);
                float bb0 = sfB2[cc], bb1 = sfB2[cc + 1];
                if (cc < NU) {
                    if (node0 < NN) {
                        float* d = st + (size_t)node0 * ND + 2;
                        float nv0 = d[cc] + acc2[f][0] + bb0;
                        float nv1 = d[cc + 1] + acc2[f][1] + bb1;
                        d[cc] = nv0; d[cc + 1] = nv1;
                        *(__half2*)(stH + (size_t)node0 * ND + 2 + cc) =
                            __floats2half2_rn(nv0, nv1);
                    }
                    if (node1 < NN) {
                        float* d = st + (size_t)node1 * ND + 2;
                        float nv0 = d[cc] + acc2[f][2] + bb0;
                        float nv1 = d[cc + 1] + acc2[f][3] + bb1;
                        d[cc] = nv0; d[cc + 1] = nv1;
                        *(__half2*)(stH + (size_t)node1 * ND + 2 + cc) =
                            __floats2half2_rn(nv0, nv1);
                    }
                }
            }
        }
        __syncthreads();
    }
}

// =====================================================================
// Readout (fp32, unchanged)
// =====================================================================
#define EXT_SMEM_FLOATS (32 * 68 + 64 * 132)
#define NSPLIT 8
#define NCHUNK (NN / NSPLIT)   // 1250

__global__ __launch_bounds__(256) void extract_kernel(
    const float* __restrict__ attn, float* __restrict__ out)
{
    extern __shared__ float sm[];
    float* sAt = sm;            // [32][68]
    float* sS  = sm + 32 * 68;  // [64][132]

    const int tid = threadIdx.x;
    const int b = blockIdx.z, qt = blockIdx.y, ns = blockIdx.x;
    const int q0 = qt * 32;
    const int nbeg = ns * NCHUNK;
    const int nend = nbeg + NCHUNK;
    const float* st = g_states + (size_t)b * NN * ND;
    const float* at = attn + ((size_t)b * NQ + q0) * NN;

    const int tc = tid & 15;
    const int tr = tid >> 4;

    float acc[2][8];
    #pragma unroll
    for (int i = 0; i < 2; i++)
        #pragma unroll
        for (int j = 0; j < 8; j++) acc[i][j] = 0.f;

    for (int n0 = nbeg; n0 < nend; n0 += 64) {
        __syncthreads();
        #pragma unroll
        for (int t = 0; t < 8; t++) {
            int idx = tid + t * 256;
            int q = idx >> 6, nn = idx & 63;
            int n = n0 + nn;
            sAt[q * 68 + nn] = (n < nend) ? at[q * NN + n] : 0.f;
        }
        #pragma unroll
        for (int t = 0; t < 32; t++) {
            int idx = tid + t * 256;
            int nn = idx >> 7, d = idx & 127;
            int n = n0 + nn;
            sS[nn * 132 + d] = (n < nend) ? st[n * ND + d] : 0.f;
        }
        __syncthreads();
        #pragma unroll 8
        for (int nn = 0; nn < 64; nn++) {
            float4 bv0 = *(const float4*)&sS[nn * 132 + tc * 8];
            float4 bv1 = *(const float4*)&sS[nn * 132 + tc * 8 + 4];
            float bb[8] = {bv0.x, bv0.y, bv0.z, bv0.w, bv1.x, bv1.y, bv1.z, bv1.w};
            float a0 = sAt[(tr * 2 + 0) * 68 + nn];
            float a1 = sAt[(tr * 2 + 1) * 68 + nn];
            #pragma unroll
            for (int j = 0; j < 8; j++) {
                acc[0][j] = fmaf(a0, bb[j], acc[0][j]);
                acc[1][j] = fmaf(a1, bb[j], acc[1][j]);
            }
        }
    }

    #pragma unroll
    for (int i = 0; i < 2; i++) {
        int q = q0 + tr * 2 + i;
        float* drow = out + ((size_t)(b * NQ + q)) * OUTC + NP + tc * 8;
        #pragma unroll
        for (int j = 0; j < 8; j++) atomicAdd(drow + j, acc[i][j]);
    }
}

// =====================================================================
extern "C" void kernel_launch(void* const* d_in, const int* in_sizes, int n_in,
                              void* d_out, int out_size)
{
    const float* nodes = (const float*)d_in[0];
    const float* poses = (const float*)d_in[1];
    const float* attn  = (const float*)d_in[2];
    const int*   esrc  = (const int*)d_in[3];
    const int*   esnk  = (const int*)d_in[4];
    const float* w1e   = (const float*)d_in[5];
    const float* b1e   = (const float*)d_in[6];
    const float* w2e   = (const float*)d_in[7];
    const float* b2e   = (const float*)d_in[8];
    const float* w1n   = (const float*)d_in[9];
    const float* b1n   = (const float*)d_in[10];
    const float* w2n   = (const float*)d_in[11];
    const float* b2n   = (const float*)d_in[12];
    float* out = (float*)d_out;

    cudaFuncSetAttribute(proj_kernel, cudaFuncAttributeMaxDynamicSharedMemorySize,
                         PROJ_SMEM_BYTES);
    cudaFuncSetAttribute(edge_kernel, cudaFuncAttributeMaxDynamicSharedMemorySize,
                         EDGE_SMEM_BYTES);
    cudaFuncSetAttribute(node_kernel, cudaFuncAttributeMaxDynamicSharedMemorySize,
                         NODE_SMEM_BYTES);

    copy_states_kernel<<<(NB * NN * ND / 4 + 255) / 256, 256>>>(nodes);

    // sink-sorted edge list (CSR), once
    csr_zero_kernel<<<(NN + 255) / 256, 256>>>();
    csr_hist_kernel<<<(NE + 255) / 256, 256>>>(esnk);
    csr_scan_kernel<<<1, 1024>>>();
    csr_scatter_kernel<<<(NE + 255) / 256, 256>>>(esrc, esnk);

    for (int s = 0; s < 3; s++) {
        zero_incoming_kernel<<<(NB * NN * NM / 4 + 255) / 256, 256>>>();
        proj_kernel<<<148, 256, PROJ_SMEM_BYTES>>>(w1e);
        edge_kernel<<<148, 512, EDGE_SMEM_BYTES>>>(b1e, w2e, b2e);
        node_kernel<<<296, 256, NODE_SMEM_BYTES>>>(w1n, b1n, w2n, b2n);
    }
    init_out_kernel<<<(NB * NQ * OUTC + 255) / 256, 256>>>(poses, out);
    extract_kernel<<<dim3(NSPLIT, NQ / 32, NB), 256, EXT_SMEM_FLOATS * 4>>>(attn, out);
}

// round 9
// speedup vs baseline: 1.3179x; 1.3179x over previous
#include <cuda_runtime.h>
#include <cuda_fp16.h>
#include <cstdint>

#define NB 4
#define NN 10000
#define NE 160000
#define NQ 256
#define ND 128
#define NM 64
#define NU 126
#define NH 128
#define NP 7
#define OUTC (NP + ND)   // 135

#define TEE 128                    // edges per edge-tile
#define NTE_B (NE / TEE)           // 1250
#define NTE_TOT (NTE_B * NB)       // 5000

#define NT_NODE_B 157              // ceil(10000/64)
#define NT_NODE_TOT (NT_NODE_B * NB)

// -------- scratch (static device globals: allocation-free) --------
__device__ float g_states[NB * NN * ND];                  // 20.5 MB
__device__ __align__(16) __half g_statesH[NB * NN * ND];  // 10.2 MB fp16 mirror
__device__ float g_incoming[NB * NN * NM];                // 10.2 MB
// CSR scratch
__device__ int g_count[NN];
__device__ int g_cur[NN];
__device__ int g_sortedSrc[NE];
__device__ int g_sortedSnk[NE];

// ============================ helpers ============================
__device__ __forceinline__ uint32_t smem_u32(const void* p) {
    uint32_t a;
    asm("{ .reg .u64 t; cvta.to.shared.u64 t, %1; cvt.u32.u64 %0, t; }"
        : "=r"(a) : "l"(p));
    return a;
}
__device__ __forceinline__ uint32_t pack_h2(float a, float b) {
    __half2 h = __floats2half2_rn(a, b);
    return *reinterpret_cast<uint32_t*>(&h);
}
__device__ __forceinline__ float tf32f(float f) {
    uint32_t r;
    asm("cvt.rna.tf32.f32 %0, %1;" : "=r"(r) : "f"(f));
    return __uint_as_float(r);
}
__device__ __forceinline__ void mma_f16(float* c, uint32_t a0, uint32_t a1,
                                        uint32_t a2, uint32_t a3,
                                        uint32_t b0, uint32_t b1) {
    asm volatile(
        "mma.sync.aligned.m16n8k16.row.col.f32.f16.f16.f32 "
        "{%0,%1,%2,%3}, {%4,%5,%6,%7}, {%8,%9}, {%0,%1,%2,%3};"
        : "+f"(c[0]), "+f"(c[1]), "+f"(c[2]), "+f"(c[3])
        : "r"(a0), "r"(a1), "r"(a2), "r"(a3), "r"(b0), "r"(b1));
}
__device__ __forceinline__ void mma_tf32(float* c, uint32_t a0, uint32_t a1,
                                         uint32_t a2, uint32_t a3,
                                         uint32_t b0, uint32_t b1) {
    asm volatile(
        "mma.sync.aligned.m16n8k8.row.col.f32.tf32.tf32.f32 "
        "{%0,%1,%2,%3}, {%4,%5,%6,%7}, {%8,%9}, {%0,%1,%2,%3};"
        : "+f"(c[0]), "+f"(c[1]), "+f"(c[2]), "+f"(c[3])
        : "r"(a0), "r"(a1), "r"(a2), "r"(a3), "r"(b0), "r"(b1));
}
#define CP_ASYNC16(dst, src) \
    asm volatile("cp.async.cg.shared.global [%0], [%1], 16;" \
                 :: "r"(dst), "l"(src) : "memory")
#define CP_COMMIT() asm volatile("cp.async.commit_group;" ::: "memory")
#define CP_WAIT0()  asm volatile("cp.async.wait_group 0;" ::: "memory")

// -------- utility kernels --------
__global__ void copy_states_kernel(const float* __restrict__ src) {
    int i = blockIdx.x * blockDim.x + threadIdx.x;
    const int n = NB * NN * ND / 4;
    if (i < n) {
        float4 v = reinterpret_cast<const float4*>(src)[i];
        reinterpret_cast<float4*>(g_states)[i] = v;
        __half2* mh = reinterpret_cast<__half2*>(g_statesH);
        mh[2 * i]     = __floats2half2_rn(v.x, v.y);
        mh[2 * i + 1] = __floats2half2_rn(v.z, v.w);
    }
}

__global__ void zero_incoming_kernel() {
    int i = blockIdx.x * blockDim.x + threadIdx.x;
    const int n = NB * NN * NM / 4;
    if (i < n) reinterpret_cast<float4*>(g_incoming)[i] = make_float4(0.f, 0.f, 0.f, 0.f);
}

__global__ void init_out_kernel(const float* __restrict__ poses, float* __restrict__ out) {
    int i = blockIdx.x * blockDim.x + threadIdx.x;
    const int n = NB * NQ * OUTC;
    if (i < n) {
        int r = i / OUTC, c = i - r * OUTC;
        out[i] = (c < NP) ? poses[r * NP + c] : 0.f;
    }
}

// -------- CSR build (once per launch; graph static) --------
__global__ void csr_zero_kernel() {
    int i = blockIdx.x * blockDim.x + threadIdx.x;
    if (i < NN) g_count[i] = 0;
}
__global__ void csr_hist_kernel(const int* __restrict__ esnk) {
    int i = blockIdx.x * blockDim.x + threadIdx.x;
    if (i < NE) atomicAdd(&g_count[esnk[i]], 1);
}
__global__ void csr_scan_kernel() {
    __shared__ int part[1024];
    int t = threadIdx.x;
    int beg = t * 10;
    int end = beg + 10 < NN ? beg + 10 : NN;
    int s = 0;
    for (int i = beg; i < end; i++) s += g_count[i];
    part[t] = s;
    __syncthreads();
    for (int d = 1; d < 1024; d <<= 1) {
        int v = (t >= d) ? part[t - d] : 0;
        __syncthreads();
        part[t] += v;
        __syncthreads();
    }
    int base = (t > 0) ? part[t - 1] : 0;
    for (int i = beg; i < end; i++) {
        g_cur[i] = base;
        base += g_count[i];
    }
}
__global__ void csr_scatter_kernel(const int* __restrict__ esrc,
                                   const int* __restrict__ esnk) {
    int i = blockIdx.x * blockDim.x + threadIdx.x;
    if (i < NE) {
        int s = esnk[i];
        int p = atomicAdd(&g_cur[s], 1);
        g_sortedSrc[p] = esrc[i];
        g_sortedSnk[p] = s;
    }
}

// =====================================================================
// Edge kernel (R7 design): persistent, 512 thr, 1 CTA/SM, fp16 mma,
// cp.async full-tile gather of statesH, sorted sinks + segmented scatter.
// =====================================================================
#define EW1   0
#define EW2   16384
#define EA    20480
#define EHH   37376
#define EMS   46080
#define EB1   54784
#define EB2   54912
#define ESNKB 54976
#define EDGE_SMEM_BYTES (55232 * 4)   // 220928

__device__ __forceinline__ void issue_gather(uint32_t aBase, int eb,
                                             const __half* __restrict__ stH,
                                             int tid) {
    #pragma unroll
    for (int i = 0; i < 8; i++) {
        int idx = tid + i * 512;            // 0..4095
        int row = idx >> 4;                 // 0..255
        int ch  = idx & 15;                 // 16B chunk within 256B row
        int e   = row & 127;
        bool snk = row >= 128;
        int node = snk ? g_sortedSnk[eb + e] : g_sortedSrc[eb + e];
        uint32_t dst = aBase + (uint32_t)(e * 528 + (snk ? 256 : 0) + ch * 16);
        const void* src = (const void*)(stH + (size_t)node * ND + ch * 8);
        CP_ASYNC16(dst, src);
    }
}

__global__ __launch_bounds__(512, 1) void edge_kernel(
    const float* __restrict__ w1, const float* __restrict__ b1,
    const float* __restrict__ w2, const float* __restrict__ b2)
{
    extern __shared__ uint32_t su[];
    float* sfB1 = (float*)(su + EB1);
    float* sfB2 = (float*)(su + EB2);
    int* sSnkB = (int*)(su + ESNKB);

    const int tid = threadIdx.x;
    const int lid = tid & 31;
    const int wid = tid >> 5;          // 0..15
    const int wg  = wid >> 1;          // 8 row groups of 16 edges
    const int wc  = wid & 1;           // column half
    const uint32_t aBase = smem_u32(su + EA);

    // prologue: issue tile-0 gather (overlaps weight staging)
    {
        int T0 = blockIdx.x;
        int b0 = T0 / NTE_B;
        int eb0 = (T0 - b0 * NTE_B) * TEE;
        const __half* stH = g_statesH + (size_t)b0 * NN * ND;
        issue_gather(aBase, eb0, stH, tid);
        if (tid < TEE) sSnkB[tid] = g_sortedSnk[eb0 + tid];
    }
    CP_COMMIT();

    // stage permuted fp16 weight fragments
    for (int i = tid; i < 16 * 16 * 32; i += 512) {
        int s = i >> 9, f = (i >> 5) & 15, l = i & 31;
        int k = s * 16 + (l & 3) * 2, n = f * 8 + (l >> 2);
        uint2 v;
        v.x = pack_h2(w1[k * NH + n],       w1[(k + 1) * NH + n]);
        v.y = pack_h2(w1[(k + 8) * NH + n], w1[(k + 9) * NH + n]);
        *(uint2*)(su + EW1 + 2 * i) = v;
    }
    for (int i = tid; i < 8 * 8 * 32; i += 512) {
        int s = i >> 8, f = (i >> 5) & 7, l = i & 31;
        int k = s * 16 + (l & 3) * 2, n = f * 8 + (l >> 2);
        uint2 v;
        v.x = pack_h2(w2[k * NM + n],       w2[(k + 1) * NM + n]);
        v.y = pack_h2(w2[(k + 8) * NM + n], w2[(k + 9) * NM + n]);
        *(uint2*)(su + EW2 + 2 * i) = v;
    }
    if (tid < NH) sfB1[tid] = b1[tid];
    else if (tid < NH + NM) sfB2[tid - NH] = b2[tid - NH];

    const int arq = wg * 16 + (lid >> 2);

    int it = 0;
    for (int T = blockIdx.x; T < NTE_TOT; T += gridDim.x, it++) {
        const int b = T / NTE_B;
        float* inc = g_incoming + (size_t)b * NN * NM;

        CP_WAIT0();
        __syncthreads();   // A tile + sSnk(buf it&1) ready; weights ready (it==0)

        // ---- GEMM1: [128e x 256k] @ [256k x 128h]
        float acc[8][4];
        #pragma unroll
        for (int f = 0; f < 8; f++)
            #pragma unroll
            for (int j = 0; j < 4; j++) acc[f][j] = 0.f;

        #pragma unroll 4
        for (int sg = 0; sg < 16; sg++) {
            const int kw = sg * 8 + (lid & 3);
            uint32_t a0 = su[EA + arq * 132 + kw];
            uint32_t a1 = su[EA + (arq + 8) * 132 + kw];
            uint32_t a2 = su[EA + arq * 132 + kw + 4];
            uint32_t a3 = su[EA + (arq + 8) * 132 + kw + 4];
            #pragma unroll
            for (int f = 0; f < 8; f++) {
                uint2 bp = *(const uint2*)(su + EW1 +
                    ((sg * 16 + wc * 8 + f) * 32 + lid) * 2);
                mma_f16(acc[f], a0, a1, a2, a3, bp.x, bp.y);
            }
        }

        // ---- epilogue1: bias + relu -> H (fp16)
        #pragma unroll
        for (int f = 0; f < 8; f++) {
            int n0 = wc * 64 + f * 8 + 2 * (lid & 3);
            float bb0 = sfB1[n0], bb1 = sfB1[n0 + 1];
            int wcol = wc * 32 + f * 4 + (lid & 3);
            su[EHH + arq * 68 + wcol] =
                pack_h2(fmaxf(acc[f][0] + bb0, 0.f), fmaxf(acc[f][1] + bb1, 0.f));
            su[EHH + (arq + 8) * 68 + wcol] =
                pack_h2(fmaxf(acc[f][2] + bb0, 0.f), fmaxf(acc[f][3] + bb1, 0.f));
        }
        __syncthreads();   // H ready; A consumed -> safe to refill

        // ---- issue next tile's gather (hidden behind GEMM2+scatter)
        {
            int Tn = T + gridDim.x;
            if (Tn < NTE_TOT) {
                int bn = Tn / NTE_B;
                int ebn = (Tn - bn * NTE_B) * TEE;
                const __half* stH = g_statesH + (size_t)bn * NN * ND;
                issue_gather(aBase, ebn, stH, tid);
                if (tid < TEE)
                    sSnkB[((it + 1) & 1) * TEE + tid] = g_sortedSnk[ebn + tid];
            }
        }
        CP_COMMIT();

        // ---- GEMM2: [128e x 128h] @ [128h x 64m]
        float acc2[4][4];
        #pragma unroll
        for (int f = 0; f < 4; f++)
            #pragma unroll
            for (int j = 0; j < 4; j++) acc2[f][j] = 0.f;

        #pragma unroll 4
        for (int sg = 0; sg < 8; sg++) {
            const int kw = sg * 8 + (lid & 3);
            uint32_t a0 = su[EHH + arq * 68 + kw];
            uint32_t a1 = su[EHH + (arq + 8) * 68 + kw];
            uint32_t a2 = su[EHH + arq * 68 + kw + 4];
            uint32_t a3 = su[EHH + (arq + 8) * 68 + kw + 4];
            #pragma unroll
            for (int f = 0; f < 4; f++) {
                uint2 bp = *(const uint2*)(su + EW2 +
                    ((sg * 8 + wc * 4 + f) * 32 + lid) * 2);
                mma_f16(acc2[f], a0, a1, a2, a3, bp.x, bp.y);
            }
        }

        // ---- epilogue2: bias -> MSG (fp32)
        float* sfMSG = (float*)(su + EMS);
        #pragma unroll
        for (int f = 0; f < 4; f++) {
            int m = wc * 32 + f * 8 + 2 * (lid & 3);
            float bb0 = sfB2[m], bb1 = sfB2[m + 1];
            sfMSG[arq * 68 + m]           = acc2[f][0] + bb0;
            sfMSG[arq * 68 + m + 1]       = acc2[f][1] + bb1;
            sfMSG[(arq + 8) * 68 + m]     = acc2[f][2] + bb0;
            sfMSG[(arq + 8) * 68 + m + 1] = acc2[f][3] + bb1;
        }
        __syncthreads();   // MSG ready

        // ---- segmented reduction over sorted sinks
        {
            const int* sSnk = sSnkB + (it & 1) * TEE;
            const int c = tid & 63;
            const int e0s = (tid >> 6) * 16;
            float part = 0.f;
            int cur = sSnk[e0s];
            #pragma unroll
            for (int j = 0; j < 16; j++) {
                part += sfMSG[(e0s + j) * 68 + c];
                int nxt = (j < 15) ? sSnk[e0s + j + 1] : -1;
                if (nxt != cur) {
                    atomicAdd(inc + (size_t)cur * NM + c, part);
                    part = 0.f;
                    cur = nxt;
                }
            }
        }
        // next iteration's top barrier orders MSG/H reuse
    }
}

// =====================================================================
// Node kernel (persistent, fp16 mma, 2 CTAs/SM) + fp16 mirror upkeep.
// NEW: zeroes its incoming rows after consumption (replaces per-step
// zero_incoming kernel; rows are block-exclusive).
// =====================================================================
#define NW1 0
#define NW2 12288
#define NA  20480
#define NHS 23040
#define NB1 27392
#define NB2 27520
#define NODE_SMEM_BYTES (27648 * 4)   // 110592

__global__ __launch_bounds__(256, 2) void node_kernel(
    const float* __restrict__ w1, const float* __restrict__ b1,
    const float* __restrict__ w2, const float* __restrict__ b2)
{
    extern __shared__ uint32_t su[];
    float* sfB1 = (float*)(su + NB1);
    float* sfB2 = (float*)(su + NB2);

    const int tid = threadIdx.x;
    const int lid = tid & 31;
    const int wid = tid >> 5;
    const int wr = wid & 3;
    const int wc = wid >> 2;

    for (int i = tid; i < 12 * 16 * 32; i += 256) {
        int s = i >> 9, f = (i >> 5) & 15, l = i & 31;
        int k = s * 16 + (l & 3) * 2, n = f * 8 + (l >> 2);
        uint2 v;
        v.x = pack_h2(w1[k * NH + n],       w1[(k + 1) * NH + n]);
        v.y = pack_h2(w1[(k + 8) * NH + n], w1[(k + 9) * NH + n]);
        *(uint2*)(su + NW1 + 2 * i) = v;
    }
    for (int i = tid; i < 8 * 16 * 32; i += 256) {
        int s = i >> 9, f = (i >> 5) & 15, l = i & 31;
        int k = s * 16 + (l & 3) * 2, n = f * 8 + (l >> 2);
        uint2 v;
        if (n < NU) {
            v.x = pack_h2(w2[k * NU + n],       w2[(k + 1) * NU + n]);
            v.y = pack_h2(w2[(k + 8) * NU + n], w2[(k + 9) * NU + n]);
        } else v.x = v.y = 0u;
        *(uint2*)(su + NW2 + 2 * i) = v;
    }
    if (tid < NH) sfB1[tid] = b1[tid];
    if (tid < 128) sfB2[tid] = (tid < NU) ? b2[tid] : 0.f;
    __syncthreads();

    const int l16 = lid & 15;
    const int rhalf = lid >> 4;

    for (int T = blockIdx.x; T < NT_NODE_TOT; T += gridDim.x) {
        const int b = T / NT_NODE_B;
        const int n0 = (T - b * NT_NODE_B) * 64;
        float* st = g_states + (size_t)b * NN * ND;
        __half* stH = g_statesH + (size_t)b * NN * ND;
        float* inc = g_incoming + (size_t)b * NN * NM;

        float acc[8][4];
        #pragma unroll
        for (int f = 0; f < 8; f++)
            #pragma unroll
            for (int j = 0; j < 4; j++) acc[f][j] = 0.f;

        float2 r[4];
        {
            #pragma unroll
            for (int i = 0; i < 4; i++) {
                int row = wid * 8 + 2 * i + rhalf;
                int node = n0 + row;
                r[i] = (node < NN) ? *(const float2*)&inc[(size_t)node * NM + l16 * 2]
                                   : make_float2(0.f, 0.f);
            }
            #pragma unroll
            for (int i = 0; i < 4; i++) {
                int row = wid * 8 + 2 * i + rhalf;
                su[NA + row * 20 + l16] = pack_h2(r[i].x, r[i].y);
            }
        }
        __syncthreads();

        const int ar = wr * 16 + (lid >> 2);
        #pragma unroll 1
        for (int c = 0; c < 6; c++) {
            if (c < 5) {
                const int cc = c + 1;
                const int g = cc * 32 + l16 * 2;
                #pragma unroll
                for (int i = 0; i < 4; i++) {
                    int row = wid * 8 + 2 * i + rhalf;
                    int node = n0 + row;
                    if (node < NN)
                        r[i] = (g < NM) ? *(const float2*)&inc[(size_t)node * NM + g]
                                        : *(const float2*)&st[(size_t)node * ND + g - NM];
                    else r[i] = make_float2(0.f, 0.f);
                }
            }
            const uint32_t* A = su + NA + (c & 1) * 1280;
            #pragma unroll
            for (int ks = 0; ks < 2; ks++) {
                const int kw = ks * 8 + (lid & 3);
                uint32_t a0 = A[ar * 20 + kw];
                uint32_t a1 = A[(ar + 8) * 20 + kw];
                uint32_t a2 = A[ar * 20 + kw + 4];
                uint32_t a3 = A[(ar + 8) * 20 + kw + 4];
                const int sg = c * 2 + ks;
                #pragma unroll
                for (int f = 0; f < 8; f++) {
                    uint2 bp = *(const uint2*)(su + NW1 +
                        ((sg * 16 + wc * 8 + f) * 32 + lid) * 2);
                    mma_f16(acc[f], a0, a1, a2, a3, bp.x, bp.y);
                }
            }
            if (c < 5) {
                uint32_t* dst = su + NA + ((c + 1) & 1) * 1280;
                #pragma unroll
                for (int i = 0; i < 4; i++) {
                    int row = wid * 8 + 2 * i + rhalf;
                    dst[row * 20 + l16] = pack_h2(r[i].x, r[i].y);
                }
            }
            __syncthreads();
        }

        // zero incoming rows (block-exclusive) for the next step
        {
            float4 z4 = make_float4(0.f, 0.f, 0.f, 0.f);
            #pragma unroll
            for (int i = 0; i < 4; i++) {
                int idx = tid + i * 256;      // 0..1023
                int row = idx >> 4, qq = idx & 15;
                int node = n0 + row;
                if (node < NN)
                    *(float4*)(inc + (size_t)node * NM + qq * 4) = z4;
            }
        }

        {
            #pragma unroll
            for (int f = 0; f < 8; f++) {
                int nn0 = wc * 64 + f * 8 + 2 * (lid & 3);
                float bb0 = sfB1[nn0], bb1 = sfB1[nn0 + 1];
                int wcol = wc * 32 + f * 4 + (lid & 3);
                su[NHS + ar * 68 + wcol] =
                    pack_h2(fmaxf(acc[f][0] + bb0, 0.f), fmaxf(acc[f][1] + bb1, 0.f));
                su[NHS + (ar + 8) * 68 + wcol] =
                    pack_h2(fmaxf(acc[f][2] + bb0, 0.f), fmaxf(acc[f][3] + bb1, 0.f));
            }
        }
        __syncthreads();

        float acc2[8][4];
        #pragma unroll
        for (int f = 0; f < 8; f++)
            #pragma unroll
            for (int j = 0; j < 4; j++) acc2[f][j] = 0.f;

        #pragma unroll 2
        for (int ks = 0; ks < 8; ks++) {
            const int kw = ks * 8 + (lid & 3);
            uint32_t a0 = su[NHS + ar * 68 + kw];
            uint32_t a1 = su[NHS + (ar + 8) * 68 + kw];
            uint32_t a2 = su[NHS + ar * 68 + kw + 4];
            uint32_t a3 = su[NHS + (ar + 8) * 68 + kw + 4];
            #pragma unroll
            for (int f = 0; f < 8; f++) {
                uint2 bp = *(const uint2*)(su + NW2 +
                    ((ks * 16 + wc * 8 + f) * 32 + lid) * 2);
                mma_f16(acc2[f], a0, a1, a2, a3, bp.x, bp.y);
            }
        }

        {
            const int node0 = n0 + ar, node1 = n0 + ar + 8;
            #pragma unroll
            for (int f = 0; f < 8; f++) {
                int cc = wc * 64 + f * 8 + 2 * (lid & 3);
                float bb0 = sfB2[cc], bb1 = sfB2[cc + 1];
                if (cc < NU) {
                    if (node0 < NN) {
                        float* d = st + (size_t)node0 * ND + 2;
                        float nv0 = d[cc] + acc2[f][0] + bb0;
                        float nv1 = d[cc + 1] + acc2[f][1] + bb1;
                        d[cc] = nv0; d[cc + 1] = nv1;
                        *(__half2*)(stH + (size_t)node0 * ND + 2 + cc) =
                            __floats2half2_rn(nv0, nv1);
                    }
                    if (node1 < NN) {
                        float* d = st + (size_t)node1 * ND + 2;
                        float nv0 = d[cc] + acc2[f][2] + bb0;
                        float nv1 = d[cc + 1] + acc2[f][3] + bb1;
                        d[cc] = nv0; d[cc + 1] = nv1;
                        *(__half2*)(stH + (size_t)node1 * ND + 2 + cc) =
                            __floats2half2_rn(nv0, nv1);
                    }
                }
            }
        }
        __syncthreads();
    }
}

// =====================================================================
// Readout: tf32 mma.sync. out[b,q,7+d] += sum_n attn[b,q,n]*states[b,n,d]
// CTA = 32 q x 128 d, split-K over 8 node ranges, atomicAdd into out.
// 8 warps: wq in {0,1} (16 q each), wd in {0..3} (32 d each).
// smem: sAt[32][68] tf32, sS[64][132] tf32.
// =====================================================================
#define EXT_SMEM_FLOATS (32 * 68 + 64 * 132)
#define NSPLIT 8
#define NCHUNK (NN / NSPLIT)   // 1250

__global__ __launch_bounds__(256) void extract_kernel(
    const float* __restrict__ attn, float* __restrict__ out)
{
    extern __shared__ float sm[];
    float* sAt = sm;            // [32][68]
    float* sS  = sm + 32 * 68;  // [64][132]

    const int tid = threadIdx.x;
    const int lid = tid & 31;
    const int wid = tid >> 5;
    const int wq = wid & 1;       // q half (16 rows)
    const int wd = wid >> 1;      // d quarter (32 cols)
    const int b = blockIdx.z, qt = blockIdx.y, ns = blockIdx.x;
    const int q0 = qt * 32;
    const int nbeg = ns * NCHUNK;
    const int nend = nbeg + NCHUNK;
    const float* st = g_states + (size_t)b * NN * ND;
    const float* at = attn + ((size_t)b * NQ + q0) * NN;

    float acc[4][4];
    #pragma unroll
    for (int f = 0; f < 4; f++)
        #pragma unroll
        for (int j = 0; j < 4; j++) acc[f][j] = 0.f;

    const int arow = wq * 16 + (lid >> 2);
    const int kq = lid & 3;

    for (int n0 = nbeg; n0 < nend; n0 += 64) {
        __syncthreads();
        #pragma unroll
        for (int t = 0; t < 8; t++) {
            int idx = tid + t * 256;
            int q = idx >> 6, nn = idx & 63;
            int n = n0 + nn;
            sAt[q * 68 + nn] = (n < nend) ? tf32f(at[q * NN + n]) : 0.f;
        }
        #pragma unroll
        for (int t = 0; t < 32; t++) {
            int idx = tid + t * 256;
            int nn = idx >> 7, d = idx & 127;
            int n = n0 + nn;
            sS[nn * 132 + d] = (n < nend) ? tf32f(st[(size_t)n * ND + d]) : 0.f;
        }
        __syncthreads();

        #pragma unroll
        for (int ks = 0; ks < 8; ks++) {
            const int k0 = ks * 8;
            uint32_t a0 = __float_as_uint(sAt[arow * 68 + k0 + kq]);
            uint32_t a1 = __float_as_uint(sAt[(arow + 8) * 68 + k0 + kq]);
            uint32_t a2 = __float_as_uint(sAt[arow * 68 + k0 + 4 + kq]);
            uint32_t a3 = __float_as_uint(sAt[(arow + 8) * 68 + k0 + 4 + kq]);
            #pragma unroll
            for (int f = 0; f < 4; f++) {
                int n = wd * 32 + f * 8 + (lid >> 2);
                uint32_t b0 = __float_as_uint(sS[(k0 + kq) * 132 + n]);
                uint32_t b1 = __float_as_uint(sS[(k0 + 4 + kq) * 132 + n]);
                mma_tf32(acc[f], a0, a1, a2, a3, b0, b1);
            }
        }
    }

    // scatter (C-frag: c0,c1 -> (row, 2(lid&3)+{0,1}); c2,c3 -> row+8)
    #pragma unroll
    for (int f = 0; f < 4; f++) {
        int d = wd * 32 + f * 8 + (lid & 3) * 2;
        int q = q0 + wq * 16 + (lid >> 2);
        float* drow = out + ((size_t)(b * NQ + q)) * OUTC + NP + d;
        atomicAdd(drow,     acc[f][0]);
        atomicAdd(drow + 1, acc[f][1]);
        float* drow2 = out + ((size_t)(b * NQ + q + 8)) * OUTC + NP + d;
        atomicAdd(drow2,     acc[f][2]);
        atomicAdd(drow2 + 1, acc[f][3]);
    }
}

// =====================================================================
extern "C" void kernel_launch(void* const* d_in, const int* in_sizes, int n_in,
                              void* d_out, int out_size)
{
    const float* nodes = (const float*)d_in[0];
    const float* poses = (const float*)d_in[1];
    const float* attn  = (const float*)d_in[2];
    const int*   esrc  = (const int*)d_in[3];
    const int*   esnk  = (const int*)d_in[4];
    const float* w1e   = (const float*)d_in[5];
    const float* b1e   = (const float*)d_in[6];
    const float* w2e   = (const float*)d_in[7];
    const float* b2e   = (const float*)d_in[8];
    const float* w1n   = (const float*)d_in[9];
    const float* b1n   = (const float*)d_in[10];
    const float* w2n   = (const float*)d_in[11];
    const float* b2n   = (const float*)d_in[12];
    float* out = (float*)d_out;

    cudaFuncSetAttribute(edge_kernel, cudaFuncAttributeMaxDynamicSharedMemorySize,
                         EDGE_SMEM_BYTES);
    cudaFuncSetAttribute(node_kernel, cudaFuncAttributeMaxDynamicSharedMemorySize,
                         NODE_SMEM_BYTES);

    copy_states_kernel<<<(NB * NN * ND / 4 + 255) / 256, 256>>>(nodes);

    // sink-sorted edge list (CSR), once
    csr_zero_kernel<<<(NN + 255) / 256, 256>>>();
    csr_hist_kernel<<<(NE + 255) / 256, 256>>>(esnk);
    csr_scan_kernel<<<1, 1024>>>();
    csr_scatter_kernel<<<(NE + 255) / 256, 256>>>(esrc, esnk);

    // one-time zero; thereafter node_kernel restores zeros each step
    zero_incoming_kernel<<<(NB * NN * NM / 4 + 255) / 256, 256>>>();

    for (int s = 0; s < 3; s++) {
        edge_kernel<<<148, 512, EDGE_SMEM_BYTES>>>(w1e, b1e, w2e, b2e);
        node_kernel<<<296, 256, NODE_SMEM_BYTES>>>(w1n, b1n, w2n, b2n);
    }
    init_out_kernel<<<(NB * NQ * OUTC + 255) / 256, 256>>>(poses, out);
    extract_kernel<<<dim3(NSPLIT, NQ / 32, NB), 256, EXT_SMEM_FLOATS * 4>>>(attn, out);
}

// round 10
// speedup vs baseline: 1.8370x; 1.3938x over previous
#include <cuda_runtime.h>
#include <cuda_fp16.h>
#include <cstdint>

#define NB 4
#define NN 10000
#define NE 160000
#define NQ 256
#define ND 128
#define NM 64
#define NU 126
#define NH 128
#define NP 7
#define OUTC (NP + ND)   // 135

#define TEE 128                    // edges per edge-tile
#define NTE_B (NE / TEE)           // 1250
#define NTE_TOT (NTE_B * NB)       // 5000

#define NT_NODE_B 157              // ceil(10000/64)
#define NT_NODE_TOT (NT_NODE_B * NB)

#define NPT_B 79                   // ceil(10000/128) proj tiles per batch
#define NPT_TOT (NPT_B * NB)       // 316

// -------- scratch (static device globals: allocation-free) --------
__device__ float g_states[NB * NN * ND];                  // 20.5 MB
__device__ __align__(16) __half g_statesH[NB * NN * ND];  // 10.2 MB fp16 mirror
__device__ float g_incoming[NB * NN * NM];                // 10.2 MB
__device__ __align__(16) __half g_P1[NB * NN * NH];       // src projections
__device__ __align__(16) __half g_P2[NB * NN * NH];       // snk projections
// CSR + tile metadata
__device__ int g_count[NN];
__device__ int g_cur[NN];
__device__ int g_sortedSrc[NE];
__device__ int g_sortedSnk[NE];
__device__ int g_li[NE];               // per-edge local unique-sink index
__device__ int g_uniq[NTE_B * TEE];    // per-tile unique sink list
__device__ int g_ucnt[NTE_B];          // per-tile unique count

// ============================ helpers ============================
__device__ __forceinline__ uint32_t smem_u32(const void* p) {
    uint32_t a;
    asm("{ .reg .u64 t; cvta.to.shared.u64 t, %1; cvt.u32.u64 %0, t; }"
        : "=r"(a) : "l"(p));
    return a;
}
__device__ __forceinline__ uint32_t pack_h2(float a, float b) {
    __half2 h = __floats2half2_rn(a, b);
    return *reinterpret_cast<uint32_t*>(&h);
}
__device__ __forceinline__ float tf32f(float f) {
    uint32_t r;
    asm("cvt.rna.tf32.f32 %0, %1;" : "=r"(r) : "f"(f));
    return __uint_as_float(r);
}
__device__ __forceinline__ void mma_f16(float* c, uint32_t a0, uint32_t a1,
                                        uint32_t a2, uint32_t a3,
                                        uint32_t b0, uint32_t b1) {
    asm volatile(
        "mma.sync.aligned.m16n8k16.row.col.f32.f16.f16.f32 "
        "{%0,%1,%2,%3}, {%4,%5,%6,%7}, {%8,%9}, {%0,%1,%2,%3};"
        : "+f"(c[0]), "+f"(c[1]), "+f"(c[2]), "+f"(c[3])
        : "r"(a0), "r"(a1), "r"(a2), "r"(a3), "r"(b0), "r"(b1));
}
__device__ __forceinline__ void mma_tf32(float* c, uint32_t a0, uint32_t a1,
                                         uint32_t a2, uint32_t a3,
                                         uint32_t b0, uint32_t b1) {
    asm volatile(
        "mma.sync.aligned.m16n8k8.row.col.f32.tf32.tf32.f32 "
        "{%0,%1,%2,%3}, {%4,%5,%6,%7}, {%8,%9}, {%0,%1,%2,%3};"
        : "+f"(c[0]), "+f"(c[1]), "+f"(c[2]), "+f"(c[3])
        : "r"(a0), "r"(a1), "r"(a2), "r"(a3), "r"(b0), "r"(b1));
}
#define CP_ASYNC16(dst, src) \
    asm volatile("cp.async.cg.shared.global [%0], [%1], 16;" \
                 :: "r"(dst), "l"(src) : "memory")
#define CP_COMMIT() asm volatile("cp.async.commit_group;" ::: "memory")
#define CP_WAIT0()  asm volatile("cp.async.wait_group 0;" ::: "memory")

// -------- utility kernels --------
__global__ void copy_states_kernel(const float* __restrict__ src) {
    int i = blockIdx.x * blockDim.x + threadIdx.x;
    const int n = NB * NN * ND / 4;
    if (i < n) {
        float4 v = reinterpret_cast<const float4*>(src)[i];
        reinterpret_cast<float4*>(g_states)[i] = v;
        __half2* mh = reinterpret_cast<__half2*>(g_statesH);
        mh[2 * i]     = __floats2half2_rn(v.x, v.y);
        mh[2 * i + 1] = __floats2half2_rn(v.z, v.w);
    }
}

__global__ void zero_incoming_kernel() {
    int i = blockIdx.x * blockDim.x + threadIdx.x;
    const int n = NB * NN * NM / 4;
    if (i < n) reinterpret_cast<float4*>(g_incoming)[i] = make_float4(0.f, 0.f, 0.f, 0.f);
}

__global__ void init_out_kernel(const float* __restrict__ poses, float* __restrict__ out) {
    int i = blockIdx.x * blockDim.x + threadIdx.x;
    const int n = NB * NQ * OUTC;
    if (i < n) {
        int r = i / OUTC, c = i - r * OUTC;
        out[i] = (c < NP) ? poses[r * NP + c] : 0.f;
    }
}

// -------- CSR build (once per launch; graph static) --------
__global__ void csr_zero_kernel() {
    int i = blockIdx.x * blockDim.x + threadIdx.x;
    if (i < NN) g_count[i] = 0;
}
__global__ void csr_hist_kernel(const int* __restrict__ esnk) {
    int i = blockIdx.x * blockDim.x + threadIdx.x;
    if (i < NE) atomicAdd(&g_count[esnk[i]], 1);
}
__global__ void csr_scan_kernel() {
    __shared__ int part[1024];
    int t = threadIdx.x;
    int beg = t * 10;
    int end = beg + 10 < NN ? beg + 10 : NN;
    int s = 0;
    for (int i = beg; i < end; i++) s += g_count[i];
    part[t] = s;
    __syncthreads();
    for (int d = 1; d < 1024; d <<= 1) {
        int v = (t >= d) ? part[t - d] : 0;
        __syncthreads();
        part[t] += v;
        __syncthreads();
    }
    int base = (t > 0) ? part[t - 1] : 0;
    for (int i = beg; i < end; i++) {
        g_cur[i] = base;
        base += g_count[i];
    }
}
__global__ void csr_scatter_kernel(const int* __restrict__ esrc,
                                   const int* __restrict__ esnk) {
    int i = blockIdx.x * blockDim.x + threadIdx.x;
    if (i < NE) {
        int s = esnk[i];
        int p = atomicAdd(&g_cur[s], 1);
        g_sortedSrc[p] = esrc[i];
        g_sortedSnk[p] = s;
    }
}
// per-tile unique-sink metadata (once)
__global__ void tile_meta_kernel() {
    __shared__ int fl[TEE];
    int t = blockIdx.x, tid = threadIdx.x;
    int e = t * TEE + tid;
    int s = g_sortedSnk[e];
    int flag = (tid == 0) || (s != g_sortedSnk[e - 1]);
    fl[tid] = flag;
    __syncthreads();
    for (int d = 1; d < TEE; d <<= 1) {
        int v = (tid >= d) ? fl[tid - d] : 0;
        __syncthreads();
        fl[tid] += v;
        __syncthreads();
    }
    int li = fl[tid] - 1;
    g_li[e] = li;
    if (flag) g_uniq[t * TEE + li] = s;
    if (tid == TEE - 1) g_ucnt[t] = fl[tid];
}

// =====================================================================
// Projection kernel: P1 = statesH @ W1top, P2 = statesH @ W1bot (fp16)
// (validated in R8). smem: PW [0,16384) frags [8 sg][32 nf][32][2];
// PA [16384, +2*8704) A bufs [128 n][68]
// =====================================================================
#define PW 0
#define PA 16384
#define PROJ_SMEM_BYTES ((16384 + 2 * 8704) * 4)   // 135168

__device__ __forceinline__ void proj_issue(uint32_t aBase, int b, int n0, int tid) {
    const __half* stH = g_statesH + (size_t)b * NN * ND;
    #pragma unroll
    for (int t = 0; t < 8; t++) {
        int idx = tid + t * 256;       // 0..2047
        int row = idx >> 4, ch = idx & 15;
        int node = n0 + row;
        if (node >= NN) node = NN - 1;   // clamp; stores are guarded
        uint32_t dst = aBase + row * 272 + ch * 16;
        CP_ASYNC16(dst, stH + (size_t)node * ND + ch * 8);
    }
}

__global__ __launch_bounds__(256, 1) void proj_kernel(
    const float* __restrict__ w1)
{
    extern __shared__ uint32_t su[];
    const int tid = threadIdx.x;
    const int lid = tid & 31;
    const int wid = tid >> 5;
    const int wm = wid >> 1;     // 4 row groups of 32 nodes
    const int wn = wid & 1;      // 2 col halves of 128 h'
    const uint32_t aBase0 = smem_u32(su + PA);

    {
        int T0 = blockIdx.x;
        if (T0 < NPT_TOT) {
            int b0 = T0 / NPT_B;
            proj_issue(aBase0, b0, (T0 - b0 * NPT_B) * 128, tid);
        }
    }
    CP_COMMIT();

    for (int i = tid; i < 8 * 32 * 32; i += 256) {
        int s = i >> 10;
        int f = (i >> 5) & 31;
        int l = i & 31;
        int colg = f * 8 + (l >> 2);
        int krow = s * 16 + (l & 3) * 2;
        int koff = (colg >= 128) ? 128 : 0;
        int col = colg & 127;
        uint2 v;
        v.x = pack_h2(w1[(koff + krow) * NH + col],     w1[(koff + krow + 1) * NH + col]);
        v.y = pack_h2(w1[(koff + krow + 8) * NH + col], w1[(koff + krow + 9) * NH + col]);
        *(uint2*)(su + PW + 2 * i) = v;
    }

    int it = 0;
    for (int T = blockIdx.x; T < NPT_TOT; T += gridDim.x, it++) {
        const int b = T / NPT_B;
        const int n0 = (T - b * NPT_B) * 128;

        CP_WAIT0();
        __syncthreads();

        {
            int Tn = T + gridDim.x;
            if (Tn < NPT_TOT) {
                int bn = Tn / NPT_B;
                proj_issue(aBase0 + ((it + 1) & 1) * 8704 * 4,
                           bn, (Tn - bn * NPT_B) * 128, tid);
            }
        }
        CP_COMMIT();

        const uint32_t* A = su + PA + (it & 1) * 8704;
        float acc[32][4];
        #pragma unroll
        for (int f = 0; f < 32; f++)
            #pragma unroll
            for (int j = 0; j < 4; j++) acc[f][j] = 0.f;

        const int r0 = wm * 32 + (lid >> 2);
        #pragma unroll
        for (int sg = 0; sg < 8; sg++) {
            const int kw = sg * 8 + (lid & 3);
            uint32_t a00 = A[r0 * 68 + kw];
            uint32_t a01 = A[(r0 + 8) * 68 + kw];
            uint32_t a02 = A[r0 * 68 + kw + 4];
            uint32_t a03 = A[(r0 + 8) * 68 + kw + 4];
            uint32_t a10 = A[(r0 + 16) * 68 + kw];
            uint32_t a11 = A[(r0 + 24) * 68 + kw];
            uint32_t a12 = A[(r0 + 16) * 68 + kw + 4];
            uint32_t a13 = A[(r0 + 24) * 68 + kw + 4];
            #pragma unroll
            for (int f = 0; f < 16; f++) {
                uint2 bp = *(const uint2*)(su + PW +
                    ((sg * 32 + wn * 16 + f) * 32 + lid) * 2);
                mma_f16(acc[f],      a00, a01, a02, a03, bp.x, bp.y);
                mma_f16(acc[16 + f], a10, a11, a12, a13, bp.x, bp.y);
            }
        }

        #pragma unroll
        for (int mf = 0; mf < 2; mf++) {
            #pragma unroll
            for (int f = 0; f < 16; f++) {
                const float* c = acc[mf * 16 + f];
                int colg = wn * 128 + f * 8 + (lid & 3) * 2;
                __half* P = (colg < 128) ? g_P1 : g_P2;
                int col = colg & 127;
                int r = wm * 32 + mf * 16 + (lid >> 2);
                int node0 = n0 + r, node1 = n0 + r + 8;
                if (node0 < NN)
                    *(uint32_t*)(P + ((size_t)b * NN + node0) * NH + col) =
                        pack_h2(c[0], c[1]);
                if (node1 < NN)
                    *(uint32_t*)(P + ((size_t)b * NN + node1) * NH + col) =
                        pack_h2(c[2], c[3]);
            }
        }
        __syncthreads();
    }
}

// =====================================================================
// Edge kernel: gather P1[src] (128 rows) + P2[unique sinks] (~8-16 rows),
// H = relu(P1+P2+b1) straight into mma A-frag registers, GEMM2,
// segmented scatter. Persistent, 512 thr, 1 CTA/SM.
// smem (u32):
//   EW2O  [0,4096)        W2 frags [8 sg][8 nf][32][2]
//   EB2O  [4096,4160)     b2 fp32
//   SLIO  [4160,4416)     2 x 128 int (local idx)
//   SSKO  [4416,4672)     2 x 128 int (sink ids)
//   EMSO  [4672,13376)    MSG fp32 [128][68]
//   GP1O  [13376,30784)   2 x [128][68]  P1 rows
//   GP2O  [30784,48192)   2 x [128][68]  P2 unique rows
// =====================================================================
#define EW2O  0
#define EB2O  4096
#define SLIO  4160
#define SSKO  4416
#define EMSO  4672
#define GP1O  13376
#define GP2O  30784
#define EDGE_SMEM_BYTES (48192 * 4)   // 192768

__device__ __forceinline__ void edge_issue(
    uint32_t gp1Base, uint32_t gp2Base, uint32_t liBase, uint32_t skBase,
    int buf, int t, int b, int tid)
{
    const int eb = t * TEE;
    const char* P1 = (const char*)(g_P1 + (size_t)b * NN * NH);
    const char* P2 = (const char*)(g_P2 + (size_t)b * NN * NH);
    uint32_t g1 = gp1Base + buf * 8704 * 4;
    uint32_t g2 = gp2Base + buf * 8704 * 4;
    #pragma unroll
    for (int i = 0; i < 4; i++) {
        int idx = tid + i * 512;        // 0..2047
        int row = idx >> 4, ch = idx & 15;
        int node = g_sortedSrc[eb + row];
        CP_ASYNC16(g1 + (uint32_t)(row * 272 + ch * 16),
                   P1 + (size_t)node * 256 + ch * 16);
    }
    int uc = g_ucnt[t] * 16;
    for (int i = tid; i < uc; i += 512) {
        int row = i >> 4, ch = i & 15;
        int node = g_uniq[t * TEE + row];
        CP_ASYNC16(g2 + (uint32_t)(row * 272 + ch * 16),
                   P2 + (size_t)node * 256 + ch * 16);
    }
    if (tid < 32)
        CP_ASYNC16(liBase + buf * 512 + tid * 16,
                   (const char*)(g_li + eb) + tid * 16);
    else if (tid < 64)
        CP_ASYNC16(skBase + buf * 512 + (tid - 32) * 16,
                   (const char*)(g_sortedSnk + eb) + (tid - 32) * 16);
}

__global__ __launch_bounds__(512, 1) void edge_kernel(
    const float* __restrict__ b1,
    const float* __restrict__ w2, const float* __restrict__ b2)
{
    extern __shared__ uint32_t su[];
    float* sfB2 = (float*)(su + EB2O);
    int* sLiB = (int*)(su + SLIO);
    int* sSnkB = (int*)(su + SSKO);
    float* sfMSG = (float*)(su + EMSO);

    const int tid = threadIdx.x;
    const int lid = tid & 31;
    const int wid = tid >> 5;          // 0..15
    const int wg  = wid >> 1;          // 8 row groups of 16 edges
    const int wc  = wid & 1;           // column half of NM
    const uint32_t gp1Base = smem_u32(su + GP1O);
    const uint32_t gp2Base = smem_u32(su + GP2O);
    const uint32_t liBase  = smem_u32(su + SLIO);
    const uint32_t skBase  = smem_u32(su + SSKO);

    // prologue: tile-0 gather (overlaps weight staging)
    {
        int T0 = blockIdx.x;
        int b0 = T0 / NTE_B;
        edge_issue(gp1Base, gp2Base, liBase, skBase, 0, T0 - b0 * NTE_B, b0, tid);
    }
    CP_COMMIT();

    // stage W2 frags + b2
    for (int i = tid; i < 8 * 8 * 32; i += 512) {
        int s = i >> 8, f = (i >> 5) & 7, l = i & 31;
        int k = s * 16 + (l & 3) * 2, n = f * 8 + (l >> 2);
        uint2 v;
        v.x = pack_h2(w2[k * NM + n],       w2[(k + 1) * NM + n]);
        v.y = pack_h2(w2[(k + 8) * NM + n], w2[(k + 9) * NM + n]);
        *(uint2*)(su + EW2O + 2 * i) = v;
    }
    if (tid < NM) sfB2[tid] = b2[tid];

    // preload b1 as half2 frags: c = 4t + (lid&3) -> halves (2c, 2c+1)
    __half2 b1r[16];
    #pragma unroll
    for (int t = 0; t < 16; t++) {
        int c = 4 * t + (lid & 3);
        b1r[t] = __floats2half2_rn(b1[2 * c], b1[2 * c + 1]);
    }

    const int arq = wg * 16 + (lid >> 2);
    const __half2 hz = __floats2half2_rn(0.f, 0.f);

    int it = 0;
    for (int T = blockIdx.x; T < NTE_TOT; T += gridDim.x, it++) {
        const int b = T / NTE_B;
        const int cb = it & 1;
        float* inc = g_incoming + (size_t)b * NN * NM;

        CP_WAIT0();
        __syncthreads();   // gather bufs cb ready; also guards MSG reuse

        // ---- H = relu(P1 + P2 + b1) directly into A-frag registers
        const uint32_t* G1 = su + GP1O + cb * 8704;
        const uint32_t* G2 = su + GP2O + cb * 8704;
        const int* sLi = sLiB + cb * TEE;
        const int li0 = sLi[arq], li1 = sLi[arq + 8];
        uint32_t hA[8][4];
        #pragma unroll
        for (int sg = 0; sg < 8; sg++) {
            const int c0 = sg * 8 + (lid & 3);
            const int c1 = c0 + 4;
            __half2 v;
            v = __hmax2(__hadd2(__hadd2(*(const __half2*)&G1[arq * 68 + c0],
                                        *(const __half2*)&G2[li0 * 68 + c0]),
                                b1r[2 * sg]), hz);
            hA[sg][0] = *(uint32_t*)&v;
            v = __hmax2(__hadd2(__hadd2(*(const __half2*)&G1[(arq + 8) * 68 + c0],
                                        *(const __half2*)&G2[li1 * 68 + c0]),
                                b1r[2 * sg]), hz);
            hA[sg][1] = *(uint32_t*)&v;
            v = __hmax2(__hadd2(__hadd2(*(const __half2*)&G1[arq * 68 + c1],
                                        *(const __half2*)&G2[li0 * 68 + c1]),
                                b1r[2 * sg + 1]), hz);
            hA[sg][2] = *(uint32_t*)&v;
            v = __hmax2(__hadd2(__hadd2(*(const __half2*)&G1[(arq + 8) * 68 + c1],
                                        *(const __half2*)&G2[li1 * 68 + c1]),
                                b1r[2 * sg + 1]), hz);
            hA[sg][3] = *(uint32_t*)&v;
        }

        // ---- issue next tile's gather (hidden behind GEMM2 + scatter)
        {
            int Tn = T + gridDim.x;
            if (Tn < NTE_TOT) {
                int bn = Tn / NTE_B;
                edge_issue(gp1Base, gp2Base, liBase, skBase,
                           cb ^ 1, Tn - bn * NTE_B, bn, tid);
            }
        }
        CP_COMMIT();

        // ---- GEMM2: [128e x 128h] @ [128h x 64m], A from registers
        float acc2[4][4];
        #pragma unroll
        for (int f = 0; f < 4; f++)
            #pragma unroll
            for (int j = 0; j < 4; j++) acc2[f][j] = 0.f;

        #pragma unroll
        for (int sg = 0; sg < 8; sg++) {
            #pragma unroll
            for (int f = 0; f < 4; f++) {
                uint2 bp = *(const uint2*)(su + EW2O +
                    ((sg * 8 + wc * 4 + f) * 32 + lid) * 2);
                mma_f16(acc2[f], hA[sg][0], hA[sg][1], hA[sg][2], hA[sg][3],
                        bp.x, bp.y);
            }
        }

        // ---- bias -> MSG (fp32)
        #pragma unroll
        for (int f = 0; f < 4; f++) {
            int m = wc * 32 + f * 8 + 2 * (lid & 3);
            float bb0 = sfB2[m], bb1 = sfB2[m + 1];
            sfMSG[arq * 68 + m]           = acc2[f][0] + bb0;
            sfMSG[arq * 68 + m + 1]       = acc2[f][1] + bb1;
            sfMSG[(arq + 8) * 68 + m]     = acc2[f][2] + bb0;
            sfMSG[(arq + 8) * 68 + m + 1] = acc2[f][3] + bb1;
        }
        __syncthreads();   // MSG ready

        // ---- segmented reduction over sorted sinks
        {
            const int* sSnk = sSnkB + cb * TEE;
            const int c = tid & 63;
            const int e0s = (tid >> 6) * 16;
            float part = 0.f;
            int cur = sSnk[e0s];
            #pragma unroll
            for (int j = 0; j < 16; j++) {
                part += sfMSG[(e0s + j) * 68 + c];
                int nxt = (j < 15) ? sSnk[e0s + j + 1] : -1;
                if (nxt != cur) {
                    atomicAdd(inc + (size_t)cur * NM + c, part);
                    part = 0.f;
                    cur = nxt;
                }
            }
        }
        // next iteration's top barrier orders MSG/sSnk reuse
    }
}

// =====================================================================
// Node kernel: full-tile cp.async pipeline (R7 recipe), 256 thr, 1 CTA/SM.
// A-tile [64 n][192 k] fp16 (cols 0..63 = incoming converted, 64..191 states).
// smem (u32):
//   NW1 [0,12288)   [12 sg][16 nf][32][2]
//   NW2 [12288,20480) [8 sg][16 nf][32][2] (cols >=126 zero)
//   NB1 [20480,20608) fp32; NB2 [20608,20736) fp32
//   NHS [20736,25088) H [64][68]
//   NAB [25088, +2*10752): per buf A[64][100] (6400) + INC fp32 [64][68] (4352)
// =====================================================================
#define NW1 0
#define NW2 12288
#define NB1 20480
#define NB2 20608
#define NHS 20736
#define NAB 25088
#define NODE_SMEM_BYTES (46592 * 4)   // 186368

__device__ __forceinline__ void node_issue(uint32_t aBase, int buf, int b,
                                           int n0, int tid) {
    const char* stH = (const char*)(g_statesH + (size_t)b * NN * ND);
    const char* inc = (const char*)(g_incoming + (size_t)b * NN * NM);
    uint32_t abuf = aBase + buf * 10752 * 4;
    uint32_t ibuf = abuf + 6400 * 4;
    #pragma unroll
    for (int i = 0; i < 4; i++) {
        int idx = tid + i * 256;   // 0..1023
        int row = idx >> 4, ch = idx & 15;
        int node = n0 + row;
        if (node < NN) {
            CP_ASYNC16(abuf + (uint32_t)(row * 400 + 128 + ch * 16),
                       stH + (size_t)node * 256 + ch * 16);
            CP_ASYNC16(ibuf + (uint32_t)(row * 272 + ch * 16),
                       inc + (size_t)node * 256 + ch * 16);
        }
    }
}

__global__ __launch_bounds__(256, 1) void node_kernel(
    const float* __restrict__ w1, const float* __restrict__ b1,
    const float* __restrict__ w2, const float* __restrict__ b2)
{
    extern __shared__ uint32_t su[];
    float* sfB1 = (float*)(su + NB1);
    float* sfB2 = (float*)(su + NB2);

    const int tid = threadIdx.x;
    const int lid = tid & 31;
    const int wid = tid >> 5;
    const int wr = wid & 3;
    const int wc = wid >> 2;
    const uint32_t aBase = smem_u32(su + NAB);

    // prologue: tile-0 gather
    {
        int T0 = blockIdx.x;
        if (T0 < NT_NODE_TOT) {
            int b0 = T0 / NT_NODE_B;
            node_issue(aBase, 0, b0, (T0 - b0 * NT_NODE_B) * 64, tid);
        }
    }
    CP_COMMIT();

    // stage weights (fp16 frags)
    for (int i = tid; i < 12 * 16 * 32; i += 256) {
        int s = i >> 9, f = (i >> 5) & 15, l = i & 31;
        int k = s * 16 + (l & 3) * 2, n = f * 8 + (l >> 2);
        uint2 v;
        v.x = pack_h2(w1[k * NH + n],       w1[(k + 1) * NH + n]);
        v.y = pack_h2(w1[(k + 8) * NH + n], w1[(k + 9) * NH + n]);
        *(uint2*)(su + NW1 + 2 * i) = v;
    }
    for (int i = tid; i < 8 * 16 * 32; i += 256) {
        int s = i >> 9, f = (i >> 5) & 15, l = i & 31;
        int k = s * 16 + (l & 3) * 2, n = f * 8 + (l >> 2);
        uint2 v;
        if (n < NU) {
            v.x = pack_h2(w2[k * NU + n],       w2[(k + 1) * NU + n]);
            v.y = pack_h2(w2[(k + 8) * NU + n], w2[(k + 9) * NU + n]);
        } else v.x = v.y = 0u;
        *(uint2*)(su + NW2 + 2 * i) = v;
    }
    if (tid < NH) sfB1[tid] = b1[tid];
    if (tid < 128) sfB2[tid] = (tid < NU) ? b2[tid] : 0.f;

    const int ar = wr * 16 + (lid >> 2);

    int it = 0;
    for (int T = blockIdx.x; T < NT_NODE_TOT; T += gridDim.x, it++) {
        const int b = T / NT_NODE_B;
        const int n0 = (T - b * NT_NODE_B) * 64;
        const int cb = it & 1;
        float* st = g_states + (size_t)b * NN * ND;
        __half* stH = g_statesH + (size_t)b * NN * ND;
        float* incF = g_incoming + (size_t)b * NN * NM;

        CP_WAIT0();
        __syncthreads();   // buf cb ready (also weights on first iter; NHS reuse)

        // convert incoming fp32 -> A cols 0..31 (u32) and zero global rows
        {
            uint32_t* A = su + NAB + cb * 10752;
            const uint32_t* INC = A + 6400;
            #pragma unroll
            for (int t = 0; t < 8; t++) {
                int idx = tid + t * 256;   // 0..2047
                int row = idx >> 5, c = idx & 31;
                const float* f2 = (const float*)&INC[row * 68 + 2 * c];
                A[row * 100 + c] = pack_h2(f2[0], f2[1]);
            }
            float4 z4 = make_float4(0.f, 0.f, 0.f, 0.f);
            #pragma unroll
            for (int t = 0; t < 4; t++) {
                int idx = tid + t * 256;   // 0..1023
                int row = idx >> 4, q = idx & 15;
                int node = n0 + row;
                if (node < NN)
                    *(float4*)(incF + (size_t)node * NM + q * 4) = z4;
            }
        }
        __syncthreads();   // A complete

        // issue next tile
        {
            int Tn = T + gridDim.x;
            if (Tn < NT_NODE_TOT) {
                int bn = Tn / NT_NODE_B;
                node_issue(aBase, cb ^ 1, bn, (Tn - bn * NT_NODE_B) * 64, tid);
            }
        }
        CP_COMMIT();

        // GEMM1: [64 x 192] @ [192 x 128], 12 K-steps, no chunk barriers
        const uint32_t* A = su + NAB + cb * 10752;
        float acc[8][4];
        #pragma unroll
        for (int f = 0; f < 8; f++)
            #pragma unroll
            for (int j = 0; j < 4; j++) acc[f][j] = 0.f;

        #pragma unroll 4
        for (int sg = 0; sg < 12; sg++) {
            const int kw = sg * 8 + (lid & 3);
            uint32_t a0 = A[ar * 100 + kw];
            uint32_t a1 = A[(ar + 8) * 100 + kw];
            uint32_t a2 = A[ar * 100 + kw + 4];
            uint32_t a3 = A[(ar + 8) * 100 + kw + 4];
            #pragma unroll
            for (int f = 0; f < 8; f++) {
                uint2 bp = *(const uint2*)(su + NW1 +
                    ((sg * 16 + wc * 8 + f) * 32 + lid) * 2);
                mma_f16(acc[f], a0, a1, a2, a3, bp.x, bp.y);
            }
        }

        // epilogue1: bias + relu -> H
        #pragma unroll
        for (int f = 0; f < 8; f++) {
            int nn0 = wc * 64 + f * 8 + 2 * (lid & 3);
            float bb0 = sfB1[nn0], bb1 = sfB1[nn0 + 1];
            int wcol = wc * 32 + f * 4 + (lid & 3);
            su[NHS + ar * 68 + wcol] =
                pack_h2(fmaxf(acc[f][0] + bb0, 0.f), fmaxf(acc[f][1] + bb1, 0.f));
            su[NHS + (ar + 8) * 68 + wcol] =
                pack_h2(fmaxf(acc[f][2] + bb0, 0.f), fmaxf(acc[f][3] + bb1, 0.f));
        }
        __syncthreads();

        // GEMM2: [64 x 128] @ [128 x 128(padded 126)]
        float acc2[8][4];
        #pragma unroll
        for (int f = 0; f < 8; f++)
            #pragma unroll
            for (int j = 0; j < 4; j++) acc2[f][j] = 0.f;

        #pragma unroll 2
        for (int ks = 0; ks < 8; ks++) {
            const int kw = ks * 8 + (lid & 3);
            uint32_t a0 = su[NHS + ar * 68 + kw];
            uint32_t a1 = su[NHS + (ar + 8) * 68 + kw];
            uint32_t a2 = su[NHS + ar * 68 + kw + 4];
            uint32_t a3 = su[NHS + (ar + 8) * 68 + kw + 4];
            #pragma unroll
            for (int f = 0; f < 8; f++) {
                uint2 bp = *(const uint2*)(su + NW2 +
                    ((ks * 16 + wc * 8 + f) * 32 + lid) * 2);
                mma_f16(acc2[f], a0, a1, a2, a3, bp.x, bp.y);
            }
        }

        // in-place state update + fp16 mirror (exclusive ownership)
        {
            const int node0 = n0 + ar, node1 = n0 + ar + 8;
            #pragma unroll
            for (int f = 0; f < 8; f++) {
                int cc = wc * 64 + f * 8 + 2 * (lid & 3);
                float bb0 = sfB2[cc], bb1 = sfB2[cc + 1];
                if (cc < NU) {
                    if (node0 < NN) {
                        float* d = st + (size_t)node0 * ND + 2;
                        float nv0 = d[cc] + acc2[f][0] + bb0;
                        float nv1 = d[cc + 1] + acc2[f][1] + bb1;
                        d[cc] = nv0; d[cc + 1] = nv1;
                        *(__half2*)(stH + (size_t)node0 * ND + 2 + cc) =
                            __floats2half2_rn(nv0, nv1);
                    }
                    if (node1 < NN) {
                        float* d = st + (size_t)node1 * ND + 2;
                        float nv0 = d[cc] + acc2[f][2] + bb0;
                        float nv1 = d[cc + 1] + acc2[f][3] + bb1;
                        d[cc] = nv0; d[cc + 1] = nv1;
                        *(__half2*)(stH + (size_t)node1 * ND + 2 + cc) =
                            __floats2half2_rn(nv0, nv1);
                    }
                }
            }
        }
        // next top barrier guards NHS reuse
    }
}

// =====================================================================
// Readout: tf32 mma.sync (unchanged from R9)
// =====================================================================
#define EXT_SMEM_FLOATS (32 * 68 + 64 * 132)
#define NSPLIT 8
#define NCHUNK (NN / NSPLIT)   // 1250

__global__ __launch_bounds__(256) void extract_kernel(
    const float* __restrict__ attn, float* __restrict__ out)
{
    extern __shared__ float sm[];
    float* sAt = sm;            // [32][68]
    float* sS  = sm + 32 * 68;  // [64][132]

    const int tid = threadIdx.x;
    const int lid = tid & 31;
    const int wid = tid >> 5;
    const int wq = wid & 1;
    const int wd = wid >> 1;
    const int b = blockIdx.z, qt = blockIdx.y, ns = blockIdx.x;
    const int q0 = qt * 32;
    const int nbeg = ns * NCHUNK;
    const int nend = nbeg + NCHUNK;
    const float* st = g_states + (size_t)b * NN * ND;
    const float* at = attn + ((size_t)b * NQ + q0) * NN;

    float acc[4][4];
    #pragma unroll
    for (int f = 0; f < 4; f++)
        #pragma unroll
        for (int j = 0; j < 4; j++) acc[f][j] = 0.f;

    const int arow = wq * 16 + (lid >> 2);
    const int kq = lid & 3;

    for (int n0 = nbeg; n0 < nend; n0 += 64) {
        __syncthreads();
        #pragma unroll
        for (int t = 0; t < 8; t++) {
            int idx = tid + t * 256;
            int q = idx >> 6, nn = idx & 63;
            int n = n0 + nn;
            sAt[q * 68 + nn] = (n < nend) ? tf32f(at[q * NN + n]) : 0.f;
        }
        #pragma unroll
        for (int t = 0; t < 32; t++) {
            int idx = tid + t * 256;
            int nn = idx >> 7, d = idx & 127;
            int n = n0 + nn;
            sS[nn * 132 + d] = (n < nend) ? tf32f(st[(size_t)n * ND + d]) : 0.f;
        }
        __syncthreads();

        #pragma unroll
        for (int ks = 0; ks < 8; ks++) {
            const int k0 = ks * 8;
            uint32_t a0 = __float_as_uint(sAt[arow * 68 + k0 + kq]);
            uint32_t a1 = __float_as_uint(sAt[(arow + 8) * 68 + k0 + kq]);
            uint32_t a2 = __float_as_uint(sAt[arow * 68 + k0 + 4 + kq]);
            uint32_t a3 = __float_as_uint(sAt[(arow + 8) * 68 + k0 + 4 + kq]);
            #pragma unroll
            for (int f = 0; f < 4; f++) {
                int n = wd * 32 + f * 8 + (lid >> 2);
                uint32_t b0 = __float_as_uint(sS[(k0 + kq) * 132 + n]);
                uint32_t b1 = __float_as_uint(sS[(k0 + 4 + kq) * 132 + n]);
                mma_tf32(acc[f], a0, a1, a2, a3, b0, b1);
            }
        }
    }

    #pragma unroll
    for (int f = 0; f < 4; f++) {
        int d = wd * 32 + f * 8 + (lid & 3) * 2;
        int q = q0 + wq * 16 + (lid >> 2);
        float* drow = out + ((size_t)(b * NQ + q)) * OUTC + NP + d;
        atomicAdd(drow,     acc[f][0]);
        atomicAdd(drow + 1, acc[f][1]);
        float* drow2 = out + ((size_t)(b * NQ + q + 8)) * OUTC + NP + d;
        atomicAdd(drow2,     acc[f][2]);
        atomicAdd(drow2 + 1, acc[f][3]);
    }
}

// =====================================================================
extern "C" void kernel_launch(void* const* d_in, const int* in_sizes, int n_in,
                              void* d_out, int out_size)
{
    const float* nodes = (const float*)d_in[0];
    const float* poses = (const float*)d_in[1];
    const float* attn  = (const float*)d_in[2];
    const int*   esrc  = (const int*)d_in[3];
    const int*   esnk  = (const int*)d_in[4];
    const float* w1e   = (const float*)d_in[5];
    const float* b1e   = (const float*)d_in[6];
    const float* w2e   = (const float*)d_in[7];
    const float* b2e   = (const float*)d_in[8];
    const float* w1n   = (const float*)d_in[9];
    const float* b1n   = (const float*)d_in[10];
    const float* w2n   = (const float*)d_in[11];
    const float* b2n   = (const float*)d_in[12];
    float* out = (float*)d_out;

    cudaFuncSetAttribute(proj_kernel, cudaFuncAttributeMaxDynamicSharedMemorySize,
                         PROJ_SMEM_BYTES);
    cudaFuncSetAttribute(edge_kernel, cudaFuncAttributeMaxDynamicSharedMemorySize,
                         EDGE_SMEM_BYTES);
    cudaFuncSetAttribute(node_kernel, cudaFuncAttributeMaxDynamicSharedMemorySize,
                         NODE_SMEM_BYTES);

    copy_states_kernel<<<(NB * NN * ND / 4 + 255) / 256, 256>>>(nodes);

    // sink-sorted edge list + tile metadata (once)
    csr_zero_kernel<<<(NN + 255) / 256, 256>>>();
    csr_hist_kernel<<<(NE + 255) / 256, 256>>>(esnk);
    csr_scan_kernel<<<1, 1024>>>();
    csr_scatter_kernel<<<(NE + 255) / 256, 256>>>(esrc, esnk);
    tile_meta_kernel<<<NTE_B, TEE>>>();

    // one-time zero; node_kernel restores zeros each step
    zero_incoming_kernel<<<(NB * NN * NM / 4 + 255) / 256, 256>>>();

    for (int s = 0; s < 3; s++) {
        proj_kernel<<<148, 256, PROJ_SMEM_BYTES>>>(w1e);
        edge_kernel<<<148, 512, EDGE_SMEM_BYTES>>>(b1e, w2e, b2e);
        node_kernel<<<148, 256, NODE_SMEM_BYTES>>>(w1n, b1n, w2n, b2n);
    }
    init_out_kernel<<<(NB * NQ * OUTC + 255) / 256, 256>>>(poses, out);
    extract_kernel<<<dim3(NSPLIT, NQ / 32, NB), 256, EXT_SMEM_FLOATS * 4>>>(attn, out);
}